// round 12
// baseline (speedup 1.0000x reference)
#include <cuda_runtime.h>
#include <math.h>

typedef unsigned long long ull;

#define T_LEN  480000
#define B_ROWS 64

// RN(1/16000): matches XLA's divide->multiply-by-reciprocal rewrite.
// Load-bearing for correctness (round-4 win) -- do not change.
#define INV_SR 6.25e-5f

// ---- packed f32x2 helpers (sm_100+; per-lane IEEE RN == scalar _rn) -------
__device__ __forceinline__ ull pk2(float lo, float hi) {
    ull r; asm("mov.b64 %0, {%1, %2};" : "=l"(r) : "f"(lo), "f"(hi)); return r;
}
__device__ __forceinline__ void up2(ull v, float& lo, float& hi) {
    asm("mov.b64 {%0, %1}, %2;" : "=f"(lo), "=f"(hi) : "l"(v));
}
__device__ __forceinline__ ull fma2(ull a, ull b, ull c) {
    ull d; asm("fma.rn.f32x2 %0, %1, %2, %3;" : "=l"(d) : "l"(a), "l"(b), "l"(c)); return d;
}
__device__ __forceinline__ ull mul2(ull a, ull b) {
    ull d; asm("mul.rn.f32x2 %0, %1, %2;" : "=l"(d) : "l"(a), "l"(b)); return d;
}
__device__ __forceinline__ ull add2(ull a, ull b) {
    ull d; asm("add.rn.f32x2 %0, %1, %2;" : "=l"(d) : "l"(a), "l"(b)); return d;
}

// Scalar per-sample tail (memory-adjacent part; packing buys nothing here).
// CHECK=false: i >= 1024 > 800 >= delay proves rp >= 0 and il >= 0.
template<bool CHECK>
__device__ __forceinline__ void sample_tail(
    const float* __restrict__ row, float* __restrict__ orow,
    int i, float posf, float dl, float mx)
{
    dl = fminf(fmaxf(dl, 1.0f), 800.0f);               // clip [1, 800]
    const float rp = __fsub_rn(posf, dl);              // ref's f32 quantization
    int il = __float2int_rd(rp);
    if (CHECK) il = max(il, 0);
    const float frac = __fsub_rn(rp, floorf(rp));

    const float a0 = __ldg(row + il);
    const float a1 = __ldg(row + il + 1);
    const float x  = __ldg(row + i);

    float d = __fmaf_rn(frac, __fsub_rn(a1, a0), a0);
    if (CHECK) d = (rp >= 0.0f) ? d : 0.0f;
    orow[i] = __fmaf_rn(mx, __fsub_rn(d, x), x);       // x + m*(d-x)
}

template<bool CHECK>
__device__ __forceinline__ void body(
    const float* __restrict__ audio, float* __restrict__ out,
    const ull* __restrict__ s_w2, const ull* __restrict__ s_d2,
    const ull* __restrict__ s_c2, const ull* __restrict__ s_m2, int i)
{
    const float posf = (float)i;                       // exact (i < 2^24)
    const float t = __fmul_rn(posf, INV_SR);           // XLA reciprocal-mul
    const ull t2 = pk2(t, t);

    // Packed constants (sine: mod-pi reduction + deg-11 odd minimax,
    // validated rounds 9/10; per-lane arithmetic bit-identical to scalar).
    const ull INVPI2 = pk2(0.31830988618379067154f, 0.31830988618379067154f);
    const ull MAGIC2 = pk2( 12582912.0f,  12582912.0f);   // 1.5*2^23
    const ull NMAGC2 = pk2(-12582912.0f, -12582912.0f);
    const ull NPIHI2 = pk2(-3.14159274101257324219f, -3.14159274101257324219f);
    const ull PILO2  = pk2(8.74227765734758577e-8f, 8.74227765734758577e-8f);
    const ull C0 = pk2(-2.3889859e-08f, -2.3889859e-08f);
    const ull C1 = pk2( 2.7525562e-06f,  2.7525562e-06f);
    const ull C2 = pk2(-1.9840874e-04f, -1.9840874e-04f);
    const ull C3 = pk2( 8.3333310e-03f,  8.3333310e-03f);
    const ull C4 = pk2(-1.6666667e-01f, -1.6666667e-01f);

    const float* row  = audio;
    float*       orow = out;

    #pragma unroll 2
    for (int pb = 0; pb < B_ROWS / 2; ++pb, row += 2 * T_LEN, orow += 2 * T_LEN) {
        // arg = ((2*pi)*rate) * t for batches (2pb, 2pb+1) in one packed mul.
        const ull arg2 = mul2(s_w2[pb], t2);

        // packed sine: jf = fma(arg, 1/pi, MAGIC); n = jf - MAGIC;
        // r = fma(n,-pi_hi,arg); r = fma(n,pi_lo,r); odd poly; sign=(-1)^n.
        const ull jf2 = fma2(arg2, INVPI2, MAGIC2);
        float jl, jh; up2(jf2, jl, jh);                 // low bits hold n
        const ull n2 = add2(jf2, NMAGC2);               // exact subtraction
        ull r2 = fma2(n2, NPIHI2, arg2);
        r2 = fma2(n2, PILO2, r2);
        const ull ss2 = mul2(r2, r2);
        ull p2 = fma2(C0, ss2, C1);
        p2 = fma2(p2, ss2, C2);
        p2 = fma2(p2, ss2, C3);
        p2 = fma2(p2, ss2, C4);
        const ull sr2 = fma2(mul2(p2, ss2), r2, r2);

        float s0, s1; up2(sr2, s0, s1);
        const float lfo0 = __int_as_float(__float_as_int(s0) ^ (__float_as_int(jl) << 31));
        const float lfo1 = __int_as_float(__float_as_int(s1) ^ (__float_as_int(jh) << 31));

        // delay = cds + ((lfo*depth)*cds) packed -- exact ref rounding order.
        const ull delay2 = add2(s_c2[pb], mul2(mul2(pk2(lfo0, lfo1), s_d2[pb]), s_c2[pb]));

        float dl0, dl1; up2(delay2, dl0, dl1);
        float mx0, mx1; up2(s_m2[pb], mx0, mx1);

        sample_tail<CHECK>(row,         orow,         i, posf, dl0, mx0);
        sample_tail<CHECK>(row + T_LEN, orow + T_LEN, i, posf, dl1, mx1);
    }
}

__global__ __launch_bounds__(256, 6)   // ~40 regs cap: room for packed consts
void chorus_kernel(const float* __restrict__ audio,
                   const float* __restrict__ rate_hz,
                   const float* __restrict__ depth,
                   const float* __restrict__ centre_ms,
                   const float* __restrict__ mix,
                   float* __restrict__ out)
{
    // Params packed per batch-pair: ull[pb] = {val_{2pb}, val_{2pb+1}}.
    // Float aliasing gives exactly that layout for sequential b writes.
    __shared__ ull s_w2[B_ROWS / 2], s_d2[B_ROWS / 2],
                   s_c2[B_ROWS / 2], s_m2[B_ROWS / 2];

    const float TWO_PI_F = 6.28318530717958647692f;    // f32 = 0x40C90FDB
    if (threadIdx.x < B_ROWS) {
        const int b = threadIdx.x;
        reinterpret_cast<float*>(s_w2)[b] = __fmul_rn(TWO_PI_F, __ldg(rate_hz + b));
        reinterpret_cast<float*>(s_d2)[b] = __ldg(depth + b);
        reinterpret_cast<float*>(s_c2)[b] = __fmul_rn(__ldg(centre_ms + b), 16.0f);
        reinterpret_cast<float*>(s_m2)[b] = __ldg(mix + b);
    }
    __syncthreads();

    const int i = blockIdx.x * 256 + threadIdx.x;      // grid covers T_LEN exactly

    // Block-uniform specialization: bid >= 4 -> i >= 1024 -> rp, il in range.
    if (blockIdx.x >= 4) body<false>(audio, out, s_w2, s_d2, s_c2, s_m2, i);
    else                 body<true >(audio, out, s_w2, s_d2, s_c2, s_m2, i);
}

extern "C" void kernel_launch(void* const* d_in, const int* in_sizes, int n_in,
                              void* d_out, int out_size)
{
    // metadata order: audio, rate_hz, depth, centre_delay_ms, feedback(unused), mix
    const float* audio     = (const float*)d_in[0];
    const float* rate_hz   = (const float*)d_in[1];
    const float* depth     = (const float*)d_in[2];
    const float* centre_ms = (const float*)d_in[3];
    const float* mix       = (const float*)d_in[5];
    float* out = (float*)d_out;

    (void)in_sizes; (void)n_in; (void)out_size;

    chorus_kernel<<<1875, 256>>>(audio, rate_hz, depth, centre_ms, mix, out);
}

// round 13
// speedup vs baseline: 1.0774x; 1.0774x over previous
#include <cuda_runtime.h>
#include <math.h>

#define T_LEN  480000
#define B_ROWS 64

// RN(1/16000): matches XLA's divide->multiply-by-reciprocal rewrite.
// Load-bearing for correctness (round-4 win) -- do not change.
#define INV_SR 6.25e-5f

// ---------------------------------------------------------------------------
// Sine = exact Cody-Waite mod-2pi reduction (mine) + hardware MUFU sin on the
// reduced argument r in [-pi, pi].
//   - Rounds 1/2 failed because __sinf does its OWN sloppy reduction at
//     |x|~424 (err ~2.6e-5). Here MUFU only ever sees |r| <= pi, where its
//     error is ~2^-21.4 ~ 3.6e-7 -- round-10 accuracy class.
//   - Reduction: magic-number round (n = round(x/2pi) <= 68, exact) + 2-term
//     CW (validated in round 8; the poly interval was that round's bug, not
//     the reduction). Constants are FFMA immediates: ZERO register cost.
//   - 6 instructions vs 13 (round-10 poly sine). No parity/sign logic.
// ---------------------------------------------------------------------------
__device__ __forceinline__ float sin_fast(float x)
{
    const float MAGIC = 12582912.0f;                   // 1.5 * 2^23
    float jf = __fmaf_rn(x, 0.15915494309189533577f, MAGIC);  // round(x/2pi)
    float n  = __fsub_rn(jf, MAGIC);

    // r = x - n*2pi, 2-term Cody-Waite (2pi_hi = f32(2pi) = 0x40C90FDB)
    float r = __fmaf_rn(n, -6.28318548202514648438f, x);
    r = __fmaf_rn(n, 1.74845560007442631e-7f, r);      // +n*(hi - 2pi)

    float s;
    asm("sin.approx.f32 %0, %1;" : "=f"(s) : "f"(r));  // MUFU on reduced arg
    return s;
}

// One (i,b) sample. CHECK=false: i >= 1024 > 800 >= delay proves rp >= 0 and
// il >= 0; skip the clamp + select.
template<bool CHECK>
__device__ __forceinline__ float chorus_sample(
    const float* __restrict__ row, int i, float posf, float t, float4 p)
{
    // arg = ((2*pi)*rate) * t -- exact reference f32 op order (p.x = 2pi*rate).
    const float arg = __fmul_rn(p.x, t);
    const float lfo = sin_fast(arg);

    // delay = cds + ((lfo*depth)*cds) -- exact ref rounding order, clip [1,800].
    float delay = __fadd_rn(p.z, __fmul_rn(__fmul_rn(lfo, p.y), p.z));
    delay = fminf(fmaxf(delay, 1.0f), 800.0f);

    const float rp = __fsub_rn(posf, delay);           // ref's f32 quantization
    int il = __float2int_rd(rp);
    if (CHECK) il = max(il, 0);
    const float frac = __fsub_rn(rp, floorf(rp));

    const float a0 = __ldg(row + il);
    const float a1 = __ldg(row + il + 1);
    const float x  = __ldg(row + i);

    float delayed = __fmaf_rn(frac, __fsub_rn(a1, a0), a0);
    if (CHECK) delayed = (rp >= 0.0f) ? delayed : 0.0f;

    // x*(1-m) + d*m == x + m*(d-x); ±1ulp direct error, un-amplified.
    return __fmaf_rn(p.w, __fsub_rn(delayed, x), x);
}

template<bool CHECK>
__device__ __forceinline__ void chorus_body(
    const float* __restrict__ audio, float* __restrict__ out,
    const float4* __restrict__ s_p, int i)
{
    const float posf = (float)i;                       // exact (i < 2^24)
    const float t = __fmul_rn(posf, INV_SR);           // XLA reciprocal-mul

    const float* row  = audio;
    float*       orow = out;

    // unroll 4: fits the 32-reg cap from __launch_bounds__(256, 8) without
    // spills. Occupancy is the binding resource (rounds 6/9/10/12).
    #pragma unroll 4
    for (int b = 0; b < B_ROWS; ++b, row += T_LEN, orow += T_LEN) {
        const float4 p = s_p[b];                       // one LDS.128 broadcast
        orow[i] = chorus_sample<CHECK>(row, i, posf, t, p);
    }
}

__global__ __launch_bounds__(256, 8)   // force <=32 regs -> 8 blocks/SM
void chorus_kernel(const float* __restrict__ audio,
                   const float* __restrict__ rate_hz,
                   const float* __restrict__ depth,
                   const float* __restrict__ centre_ms,
                   const float* __restrict__ mix,
                   float* __restrict__ out)
{
    __shared__ float4 s_p[B_ROWS];                     // {2pi*rate, depth, cds, mix}

    const float TWO_PI_F = 6.28318530717958647692f;    // f32 = 0x40C90FDB
    if (threadIdx.x < B_ROWS) {
        const int b = threadIdx.x;
        float4 p;
        p.x = __fmul_rn(TWO_PI_F, __ldg(rate_hz + b));
        p.y = __ldg(depth + b);
        p.z = __fmul_rn(__ldg(centre_ms + b), 16.0f);
        p.w = __ldg(mix + b);
        s_p[b] = p;
    }
    __syncthreads();

    const int i = blockIdx.x * blockDim.x + threadIdx.x;
    if (i >= T_LEN) return;

    // Block-uniform specialization: bid >= 4 -> i >= 1024 -> rp, il in range.
    if (blockIdx.x >= 4) chorus_body<false>(audio, out, s_p, i);
    else                 chorus_body<true >(audio, out, s_p, i);
}

extern "C" void kernel_launch(void* const* d_in, const int* in_sizes, int n_in,
                              void* d_out, int out_size)
{
    // metadata order: audio, rate_hz, depth, centre_delay_ms, feedback(unused), mix
    const float* audio     = (const float*)d_in[0];
    const float* rate_hz   = (const float*)d_in[1];
    const float* depth     = (const float*)d_in[2];
    const float* centre_ms = (const float*)d_in[3];
    const float* mix       = (const float*)d_in[5];
    float* out = (float*)d_out;

    (void)in_sizes; (void)n_in; (void)out_size;

    const int threads = 256;
    const int blocks  = (T_LEN + threads - 1) / threads;   // 1875
    chorus_kernel<<<blocks, threads>>>(audio, rate_hz, depth, centre_ms, mix, out);
}